// round 7
// baseline (speedup 1.0000x reference)
#include <cuda_runtime.h>
#include <cuda_fp16.h>

#define D 64
#define NODES_MAX 100000
#define MAXDEG 64
#define FIXSCALE 16777216.0f      // 2^24
#define FIXINV   5.9604645e-8f    // 2^-24

// ---- scratch (static __device__; no allocation anywhere) ----
__device__ float2 g_st[NODES_MAX];                 // {s, t}
__device__ unsigned long long g_pack[NODES_MAX];   // {cnt:hi32, diag_fix:lo32}
__device__ float g_dsi[NODES_MAX];
__device__ float g_diag[NODES_MAX];
__device__ __half g_yh[(size_t)NODES_MAX * D];     // y, later scaled to dsi*y
__device__ float2 g_bkt[(size_t)NODES_MAX * MAXDEG]; // {col_as_int_bits, m1*m2}

// K1: per-node precompute. yh = fp16(x @ W_lin^T + b); st = {x.WsA, x.WsB};
// zero pack.
__global__ void k_node_pre(const float* __restrict__ x,
                           const float* __restrict__ Ws,
                           const float* __restrict__ Wl,
                           const float* __restrict__ bl,
                           int N) {
    __shared__ float xs[4][D];
    const int g    = threadIdx.x >> 6;
    const int j    = threadIdx.x & 63;
    const int lane = threadIdx.x & 31;

    float w[D];
    #pragma unroll
    for (int k = 0; k < D; k += 4) {
        float4 v = *(const float4*)(Wl + j * D + k);
        w[k] = v.x; w[k + 1] = v.y; w[k + 2] = v.z; w[k + 3] = v.w;
    }
    const float bj = bl[j];
    const float wsA0 = Ws[lane],      wsA1 = Ws[lane + 32];
    const float wsB0 = Ws[64 + lane], wsB1 = Ws[96 + lane];

    for (int base = blockIdx.x * 4; base < N; base += gridDim.x * 4) {
        const int  node  = base + g;
        const bool valid = (node < N);
        __syncthreads();
        if (valid && j < 16)
            ((float4*)xs[g])[j] = ((const float4*)(x + (size_t)node * D))[j];
        __syncthreads();

        float acc = bj;
        #pragma unroll
        for (int k = 0; k < D; k++) acc = fmaf(xs[g][k], w[k], acc);
        if (valid) g_yh[(size_t)node * D + j] = __float2half(acc);

        if (j < 32) {
            const float x0 = xs[g][lane], x1 = xs[g][lane + 32];
            float ps = x0 * wsA0 + x1 * wsA1;
            float pt = x0 * wsB0 + x1 * wsB1;
            #pragma unroll
            for (int off = 16; off; off >>= 1) {
                ps += __shfl_down_sync(0xffffffffu, ps, off);
                pt += __shfl_down_sync(0xffffffffu, pt, off);
            }
            if (lane == 0 && valid) {
                g_st[node]   = make_float2(ps, pt);
                g_pack[node] = 0ULL;
            }
        }
    }
}

// K2: per pair: packed u64 atomic per endpoint {cnt++, diag += m^2} returns the
// bucket slot; write {col, w} directly into the fixed-stride bucket.
__global__ void k_edge_maps(const int* __restrict__ src,
                            const int* __restrict__ dst,
                            int Eh) {
    int e = blockIdx.x * blockDim.x + threadIdx.x;
    if (e >= Eh) return;
    const int a = src[e], b = dst[e];
    const float2 sta = g_st[a];
    const float2 stb = g_st[b];
    const float m1 = tanhf(sta.x + stb.y);   // s[a] + t[b]
    const float m2 = tanhf(stb.x + sta.y);   // s[b] + t[a]
    const float w  = m1 * m2;
    const unsigned u1 = __float2uint_rn(m1 * m1 * FIXSCALE);
    const unsigned u2 = __float2uint_rn(m2 * m2 * FIXSCALE);
    const unsigned long long olda = atomicAdd(&g_pack[a], (1ULL << 32) | u1);
    const unsigned long long oldb = atomicAdd(&g_pack[b], (1ULL << 32) | u2);
    const int sa = (int)(olda >> 32);
    const int sb = (int)(oldb >> 32);
    float2 ea; ea.x = __int_as_float(b); ea.y = w;
    float2 eb; eb.x = __int_as_float(a); eb.y = w;
    g_bkt[(size_t)a * MAXDEG + sa] = ea;
    g_bkt[(size_t)b * MAXDEG + sb] = eb;
}

// K3: decode pack -> diag/dsi; scale yh rows by dsi (warp-cooperative).
// One warp handles 32 consecutive nodes. Block 256 = 8 warps = 256 nodes.
__global__ void k_scale(int N) {
    const int lane = threadIdx.x & 31;
    const int wid  = threadIdx.x >> 5;
    const int node_base = (blockIdx.x * 8 + wid) * 32;
    const int i = node_base + lane;

    float dsi = 1.f;
    if (i < N) {
        const unsigned long long pk = g_pack[i];
        const float dg = (float)(unsigned)(pk & 0xffffffffu) * FIXINV;
        dsi = rsqrtf(dg + 1.f);
        g_diag[i] = dg;
        g_dsi[i]  = dsi;
    }
    #pragma unroll 4
    for (int r = 0; r < 32; r++) {
        const int node = node_base + r;
        if (node >= N) break;
        const float dr = __shfl_sync(0xffffffffu, dsi, r);
        __half2* p = ((__half2*)g_yh) + (size_t)node * 32 + lane;
        const float2 val = __half22float2(*p);
        *p = __floats2half2_rn(val.x * dr, val.y * dr);
    }
}

// K4: fused gather. Half-warp (16 lanes) per node, lane owns 4 cols.
// Meta entries loaded coalesced (16 at a time) then shfl-broadcast.
// out[n] = x[n] - (dg*dsi)*yh'[n] + dsi * sum_k w_k * yh'[col_k]
__global__ void k_gather(const float* __restrict__ x,
                         float* __restrict__ out, int N) {
    const int node = (blockIdx.x * blockDim.x + threadIdx.x) >> 4;
    if (node >= N) return;
    const int l16 = threadIdx.x & 15;

    const int deg = (int)(g_pack[node] >> 32);
    const float2* __restrict__ row = g_bkt + (size_t)node * MAXDEG;

    float a0 = 0.f, a1 = 0.f, a2 = 0.f, a3 = 0.f;

    for (int k0 = 0; k0 < deg; k0 += 16) {
        const int nloc = deg - k0;
        float2 m = make_float2(0.f, 0.f);
        if (l16 < nloc) m = row[k0 + l16];          // coalesced 128B per half-warp
        if (nloc >= 16) {
            #pragma unroll
            for (int r = 0; r < 16; r++) {
                const int   c = __float_as_int(__shfl_sync(0xffffffffu, m.x, r, 16));
                const float wv = __shfl_sync(0xffffffffu, m.y, r, 16);
                const uint2 rv = *((const uint2*)(g_yh + (size_t)c * D) + l16);
                const float2 fa = __half22float2(*(const __half2*)&rv.x);
                const float2 fb = __half22float2(*(const __half2*)&rv.y);
                a0 = fmaf(wv, fa.x, a0); a1 = fmaf(wv, fa.y, a1);
                a2 = fmaf(wv, fb.x, a2); a3 = fmaf(wv, fb.y, a3);
            }
        } else {
            for (int r = 0; r < nloc; r++) {
                const int   c = __float_as_int(__shfl_sync(0xffffffffu, m.x, r, 16));
                const float wv = __shfl_sync(0xffffffffu, m.y, r, 16);
                const uint2 rv = *((const uint2*)(g_yh + (size_t)c * D) + l16);
                const float2 fa = __half22float2(*(const __half2*)&rv.x);
                const float2 fb = __half22float2(*(const __half2*)&rv.y);
                a0 = fmaf(wv, fa.x, a0); a1 = fmaf(wv, fa.y, a1);
                a2 = fmaf(wv, fb.x, a2); a3 = fmaf(wv, fb.y, a3);
            }
        }
    }

    const float dg   = g_diag[node];
    const float dsi  = g_dsi[node];
    const float cown = dg * dsi;   // cd/dsi
    const uint2 ro = *((const uint2*)(g_yh + (size_t)node * D) + l16);
    const float2 ya = __half22float2(*(const __half2*)&ro.x);
    const float2 yb = __half22float2(*(const __half2*)&ro.y);
    const float4 xv = *((const float4*)(x + (size_t)node * D) + l16);
    float4 o;
    o.x = xv.x - cown * ya.x + dsi * a0;
    o.y = xv.y - cown * ya.y + dsi * a1;
    o.z = xv.z - cown * yb.x + dsi * a2;
    o.w = xv.w - cown * yb.y + dsi * a3;
    *((float4*)(out + (size_t)node * D) + l16) = o;
}

extern "C" void kernel_launch(void* const* d_in, const int* in_sizes, int n_in,
                              void* d_out, int out_size) {
    const float* x  = (const float*)d_in[0];
    const float* Ws = (const float*)d_in[1];
    const float* Wl = (const float*)d_in[2];
    const float* bl = (const float*)d_in[3];
    const int*   ei = (const int*)d_in[4];

    const int N  = in_sizes[0] / D;
    const int E  = in_sizes[4] / 2;
    const int Eh = E / 2;
    const int* src = ei;           // row[e] for e < Eh
    const int* dst = ei + E;       // col[e] for e < Eh

    k_node_pre<<<1184, 256>>>(x, Ws, Wl, bl, N);
    k_edge_maps<<<(Eh + 255) / 256, 256>>>(src, dst, Eh);
    k_scale<<<(N + 255) / 256, 256>>>(N);
    k_gather<<<(N * 16 + 255) / 256, 256>>>(x, (float*)d_out, N);
}

// round 8
// speedup vs baseline: 1.2124x; 1.2124x over previous
#include <cuda_runtime.h>
#include <cuda_fp16.h>

#define D 64
#define NODES_MAX 100000
#define EDGES_MAX 1600000
#define SCAN_BLK 1024
#define NB_MAX   128
#define FIXSCALE 16777216.0f      // 2^24
#define FIXINV   5.9604645e-8f    // 2^-24

// ---- scratch (static __device__; no allocation anywhere) ----
__device__ float2 g_st[NODES_MAX];                 // {s, t}
__device__ unsigned long long g_pack[NODES_MAX];   // {cnt:hi32, diag_fix:lo32}
__device__ float g_dsi[NODES_MAX];
__device__ float g_diag[NODES_MAX];
__device__ int   g_off[NODES_MAX];
__device__ int   g_bsum[NB_MAX];
__device__ int   g_boff[NB_MAX];
__device__ unsigned g_scan_ctr;
__device__ float g_w[EDGES_MAX / 2];               // m1*m2 per pair (raw)
__device__ int   g_slota[EDGES_MAX / 2];
__device__ int   g_slotb[EDGES_MAX / 2];
__device__ __half g_yh[(size_t)NODES_MAX * D];     // y, later scaled to dsi*y
__device__ float2 g_csr[EDGES_MAX];                // {col_as_int_bits, m1*m2}

// K1: per-node precompute. yh = fp16(x @ W_lin^T + b); st = {x.WsA, x.WsB};
// zero pack; reset scan counter.
__global__ void k_node_pre(const float* __restrict__ x,
                           const float* __restrict__ Ws,
                           const float* __restrict__ Wl,
                           const float* __restrict__ bl,
                           int N) {
    if (blockIdx.x == 0 && threadIdx.x == 0) g_scan_ctr = 0;
    __shared__ float xs[4][D];
    const int g    = threadIdx.x >> 6;
    const int j    = threadIdx.x & 63;
    const int lane = threadIdx.x & 31;

    float w[D];
    #pragma unroll
    for (int k = 0; k < D; k += 4) {
        float4 v = *(const float4*)(Wl + j * D + k);
        w[k] = v.x; w[k + 1] = v.y; w[k + 2] = v.z; w[k + 3] = v.w;
    }
    const float bj = bl[j];
    const float wsA0 = Ws[lane],      wsA1 = Ws[lane + 32];
    const float wsB0 = Ws[64 + lane], wsB1 = Ws[96 + lane];

    for (int base = blockIdx.x * 4; base < N; base += gridDim.x * 4) {
        const int  node  = base + g;
        const bool valid = (node < N);
        __syncthreads();
        if (valid && j < 16)
            ((float4*)xs[g])[j] = ((const float4*)(x + (size_t)node * D))[j];
        __syncthreads();

        float acc = bj;
        #pragma unroll
        for (int k = 0; k < D; k++) acc = fmaf(xs[g][k], w[k], acc);
        if (valid) g_yh[(size_t)node * D + j] = __float2half(acc);

        if (j < 32) {
            const float x0 = xs[g][lane], x1 = xs[g][lane + 32];
            float ps = x0 * wsA0 + x1 * wsA1;
            float pt = x0 * wsB0 + x1 * wsB1;
            #pragma unroll
            for (int off = 16; off; off >>= 1) {
                ps += __shfl_down_sync(0xffffffffu, ps, off);
                pt += __shfl_down_sync(0xffffffffu, pt, off);
            }
            if (lane == 0 && valid) {
                g_st[node]   = make_float2(ps, pt);
                g_pack[node] = 0ULL;
            }
        }
    }
}

// K2: per pair: one packed u64 atomic per endpoint {cnt++, diag += m^2}
// returns the CSR slot.
__global__ void k_edge_maps(const int* __restrict__ src,
                            const int* __restrict__ dst,
                            int Eh) {
    int e = blockIdx.x * blockDim.x + threadIdx.x;
    if (e >= Eh) return;
    const int a = src[e], b = dst[e];
    const float2 sta = g_st[a];
    const float2 stb = g_st[b];
    const float m1 = tanhf(sta.x + stb.y);   // s[a] + t[b]
    const float m2 = tanhf(stb.x + sta.y);   // s[b] + t[a]
    g_w[e] = m1 * m2;
    const unsigned u1 = __float2uint_rn(m1 * m1 * FIXSCALE);
    const unsigned u2 = __float2uint_rn(m2 * m2 * FIXSCALE);
    const unsigned long long olda = atomicAdd(&g_pack[a], (1ULL << 32) | u1);
    const unsigned long long oldb = atomicAdd(&g_pack[b], (1ULL << 32) | u2);
    g_slota[e] = (int)(olda >> 32);
    g_slotb[e] = (int)(oldb >> 32);
}

// K3: decode pack -> cnt/diag/dsi; block scan of counts; scale yh by dsi
// (warp-cooperative, coalesced); last block scans block sums into g_boff.
__global__ void k_scan(int N, int nb) {
    __shared__ int warpsum[32];
    __shared__ bool is_last;
    const int tid = threadIdx.x, lane = tid & 31, wid = tid >> 5;
    const int i = blockIdx.x * SCAN_BLK + tid;

    unsigned long long pk = (i < N) ? g_pack[i] : 0ULL;
    const int   v   = (int)(pk >> 32);
    const float dg  = (float)(unsigned)(pk & 0xffffffffu) * FIXINV;
    const float dsi = rsqrtf(dg + 1.f);
    if (i < N) { g_diag[i] = dg; g_dsi[i] = dsi; }

    // scale yh rows of this warp's 32 nodes by their dsi (coalesced per row)
    {
        const int warp_base = blockIdx.x * SCAN_BLK + wid * 32;
        #pragma unroll 4
        for (int r = 0; r < 32; r++) {
            const int node = warp_base + r;
            if (node >= N) break;
            const float dr = __shfl_sync(0xffffffffu, dsi, r);
            __half2* p = ((__half2*)g_yh) + (size_t)node * 32 + lane;
            const float2 val = __half22float2(*p);
            *p = __floats2half2_rn(val.x * dr, val.y * dr);
        }
    }

    int xinc = v;
    #pragma unroll
    for (int o = 1; o < 32; o <<= 1) {
        int y = __shfl_up_sync(0xffffffffu, xinc, o);
        if (lane >= o) xinc += y;
    }
    if (lane == 31) warpsum[wid] = xinc;
    __syncthreads();
    if (wid == 0) {
        int wv = warpsum[lane];
        #pragma unroll
        for (int o = 1; o < 32; o <<= 1) {
            int y = __shfl_up_sync(0xffffffffu, wv, o);
            if (lane >= o) wv += y;
        }
        warpsum[lane] = wv;
    }
    __syncthreads();
    const int excl = xinc - v + (wid ? warpsum[wid - 1] : 0);
    if (i < N) g_off[i] = excl;
    if (tid == SCAN_BLK - 1) g_bsum[blockIdx.x] = excl + v;

    if (tid == 0) {
        __threadfence();
        is_last = (atomicAdd(&g_scan_ctr, 1u) == (unsigned)(nb - 1));
    }
    __syncthreads();
    if (is_last && tid < 128) {
        __shared__ int ws2[4];
        const int bv = (tid < nb) ? g_bsum[tid] : 0;
        int bx = bv;
        #pragma unroll
        for (int o = 1; o < 32; o <<= 1) {
            int y = __shfl_up_sync(0xffffffffu, bx, o);
            if (lane >= o) bx += y;
        }
        if (lane == 31) ws2[tid >> 5] = bx;
        __syncthreads();
        int add = 0;
        for (int k = 0; k < (tid >> 5); k++) add += ws2[k];
        if (tid < nb) g_boff[tid] = bx - bv + add;
    }
}

// K4: atomic-free fill, raw weights (dsi folded into yh).
__global__ void k_fill_pair(const int* __restrict__ src,
                            const int* __restrict__ dst,
                            int Eh) {
    int e = blockIdx.x * blockDim.x + threadIdx.x;
    if (e >= Eh) return;
    const int a = src[e], b = dst[e];
    const float w = g_w[e];
    const int pa = g_off[a] + g_boff[a >> 10] + g_slota[e];
    const int pb = g_off[b] + g_boff[b >> 10] + g_slotb[e];
    float2 ea; ea.x = __int_as_float(b); ea.y = w;
    float2 eb; eb.x = __int_as_float(a); eb.y = w;
    g_csr[pa] = ea;
    g_csr[pb] = eb;
}

// K5: fused gather. Half-warp (16 lanes) per node, lane owns 4 cols.
// 4 independent meta+row load pairs in flight (MLP=4).
// out[n] = x[n] - (dg*dsi)*yh'[n] + dsi * sum_k w_k * yh'[col_k]
__global__ void k_gather(const float* __restrict__ x,
                         float* __restrict__ out, int N) {
    const int node = (blockIdx.x * blockDim.x + threadIdx.x) >> 4;
    if (node >= N) return;
    const int l16 = threadIdx.x & 15;

    const int start = g_off[node] + g_boff[node >> 10];
    const int kend  = start + (int)(g_pack[node] >> 32);

    float a0 = 0.f, a1 = 0.f, a2 = 0.f, a3 = 0.f;
    int k = start;
    for (; k + 4 <= kend; k += 4) {
        const float2 m0 = __ldg(&g_csr[k + 0]);
        const float2 m1 = __ldg(&g_csr[k + 1]);
        const float2 m2 = __ldg(&g_csr[k + 2]);
        const float2 m3 = __ldg(&g_csr[k + 3]);
        const uint2 r0 = __ldg((const uint2*)(g_yh + (size_t)__float_as_int(m0.x) * D) + l16);
        const uint2 r1 = __ldg((const uint2*)(g_yh + (size_t)__float_as_int(m1.x) * D) + l16);
        const uint2 r2 = __ldg((const uint2*)(g_yh + (size_t)__float_as_int(m2.x) * D) + l16);
        const uint2 r3 = __ldg((const uint2*)(g_yh + (size_t)__float_as_int(m3.x) * D) + l16);
        {
            const float2 fa = __half22float2(*(const __half2*)&r0.x);
            const float2 fb = __half22float2(*(const __half2*)&r0.y);
            a0 = fmaf(m0.y, fa.x, a0); a1 = fmaf(m0.y, fa.y, a1);
            a2 = fmaf(m0.y, fb.x, a2); a3 = fmaf(m0.y, fb.y, a3);
        }
        {
            const float2 fa = __half22float2(*(const __half2*)&r1.x);
            const float2 fb = __half22float2(*(const __half2*)&r1.y);
            a0 = fmaf(m1.y, fa.x, a0); a1 = fmaf(m1.y, fa.y, a1);
            a2 = fmaf(m1.y, fb.x, a2); a3 = fmaf(m1.y, fb.y, a3);
        }
        {
            const float2 fa = __half22float2(*(const __half2*)&r2.x);
            const float2 fb = __half22float2(*(const __half2*)&r2.y);
            a0 = fmaf(m2.y, fa.x, a0); a1 = fmaf(m2.y, fa.y, a1);
            a2 = fmaf(m2.y, fb.x, a2); a3 = fmaf(m2.y, fb.y, a3);
        }
        {
            const float2 fa = __half22float2(*(const __half2*)&r3.x);
            const float2 fb = __half22float2(*(const __half2*)&r3.y);
            a0 = fmaf(m3.y, fa.x, a0); a1 = fmaf(m3.y, fa.y, a1);
            a2 = fmaf(m3.y, fb.x, a2); a3 = fmaf(m3.y, fb.y, a3);
        }
    }
    for (; k < kend; k++) {
        const float2 m0 = __ldg(&g_csr[k]);
        const uint2 r0 = __ldg((const uint2*)(g_yh + (size_t)__float_as_int(m0.x) * D) + l16);
        const float2 fa = __half22float2(*(const __half2*)&r0.x);
        const float2 fb = __half22float2(*(const __half2*)&r0.y);
        a0 = fmaf(m0.y, fa.x, a0); a1 = fmaf(m0.y, fa.y, a1);
        a2 = fmaf(m0.y, fb.x, a2); a3 = fmaf(m0.y, fb.y, a3);
    }

    const float dg   = g_diag[node];
    const float dsi  = g_dsi[node];
    const float cown = dg * dsi;   // cd/dsi
    const uint2 ro = *((const uint2*)(g_yh + (size_t)node * D) + l16);
    const float2 ya = __half22float2(*(const __half2*)&ro.x);
    const float2 yb = __half22float2(*(const __half2*)&ro.y);
    const float4 xv = *((const float4*)(x + (size_t)node * D) + l16);
    float4 o;
    o.x = xv.x - cown * ya.x + dsi * a0;
    o.y = xv.y - cown * ya.y + dsi * a1;
    o.z = xv.z - cown * yb.x + dsi * a2;
    o.w = xv.w - cown * yb.y + dsi * a3;
    *((float4*)(out + (size_t)node * D) + l16) = o;
}

extern "C" void kernel_launch(void* const* d_in, const int* in_sizes, int n_in,
                              void* d_out, int out_size) {
    const float* x  = (const float*)d_in[0];
    const float* Ws = (const float*)d_in[1];
    const float* Wl = (const float*)d_in[2];
    const float* bl = (const float*)d_in[3];
    const int*   ei = (const int*)d_in[4];

    const int N  = in_sizes[0] / D;
    const int E  = in_sizes[4] / 2;
    const int Eh = E / 2;
    const int* src = ei;           // row[e] for e < Eh
    const int* dst = ei + E;       // col[e] for e < Eh

    const int nb = (N + SCAN_BLK - 1) / SCAN_BLK;

    k_node_pre<<<1184, 256>>>(x, Ws, Wl, bl, N);
    k_edge_maps<<<(Eh + 255) / 256, 256>>>(src, dst, Eh);
    k_scan<<<nb, SCAN_BLK>>>(N, nb);
    k_fill_pair<<<(Eh + 255) / 256, 256>>>(src, dst, Eh);
    k_gather<<<(N * 16 + 255) / 256, 256>>>(x, (float*)d_out, N);
}